// round 11
// baseline (speedup 1.0000x reference)
#include <cuda_runtime.h>
#include <cuda_bf16.h>
#include <cuda_fp16.h>
#include <cstdint>
#include <cstddef>

#define NN   50000
#define NE   800000
#define DD   128
#define KK   256
#define NBLK 49          // ceil(NN/1024)

// ================= low-level helpers =================
__device__ __forceinline__ uint32_t smem_u32(const void* p) {
    uint32_t a;
    asm("{ .reg .u64 t; cvta.to.shared.u64 t, %1; cvt.u32.u64 %0, t; }" : "=r"(a) : "l"(p));
    return a;
}
__device__ __forceinline__ void ldsm4(uint32_t* r, uint32_t addr) {
    asm volatile("ldmatrix.sync.aligned.m8n8.x4.shared.b16 {%0,%1,%2,%3}, [%4];"
                 : "=r"(r[0]), "=r"(r[1]), "=r"(r[2]), "=r"(r[3]) : "r"(addr));
}
__device__ __forceinline__ void mma16816(float* d, const uint32_t* a, uint32_t b0, uint32_t b1) {
    asm volatile(
        "mma.sync.aligned.m16n8k16.row.col.f32.bf16.bf16.f32 "
        "{%0,%1,%2,%3}, {%4,%5,%6,%7}, {%8,%9}, {%0,%1,%2,%3};"
        : "+f"(d[0]), "+f"(d[1]), "+f"(d[2]), "+f"(d[3])
        : "r"(a[0]), "r"(a[1]), "r"(a[2]), "r"(a[3]), "r"(b0), "r"(b1));
}
__device__ __forceinline__ void cpa16(uint32_t dst, const void* src, int sz) {
    asm volatile("cp.async.cg.shared.global [%0], [%1], 16, %2;"
                 :: "r"(dst), "l"(src), "r"(sz));
}
#define CPA_COMMIT() asm volatile("cp.async.commit_group;" ::: "memory")

// ================= device scratch =================
__device__ int   g_cnt[NN];
__device__ int   g_off[NN + 1];
__device__ int   g_bsum[NBLK];
__device__ int   g_bpre[NBLK];
__device__ int   g_col[NE];
__device__ float g_wgt[NE];
__device__ __half g_xf16[NN * DD];                   // fp16 x (agg gather, layer 0)
__device__ __half g_hf16[NN * DD];                   // fp16 hidden (agg gather, layers 1/2)
__device__ __nv_bfloat16 g_xhA[NN * DD], g_xlA[NN * DD];   // GEMM input split (ping)
__device__ __nv_bfloat16 g_xhB[NN * DD], g_xlB[NN * DD];   // (pong)
__device__ __nv_bfloat16 g_ah[NN * DD],  g_al[NN * DD];    // agg split
__device__ __nv_bfloat16 g_Wh0[128 * KK], g_Wl0[128 * KK];
__device__ __nv_bfloat16 g_Wh1[128 * KK], g_Wl1[128 * KK];
__device__ __nv_bfloat16 g_Wh2[64 * KK],  g_Wl2[64 * KK];

// ================= weight split (plain [n][k] layout) =================
__global__ void prep_W(const float* __restrict__ W0,
                       const float* __restrict__ W1,
                       const float* __restrict__ W2) {
    int i = blockIdx.x * 256 + threadIdx.x;
    const int L = 128 * KK;
    float w; __nv_bfloat16 *dh, *dl; int j;
    if (i < L)               { j = i;         w = W0[j]; dh = g_Wh0; dl = g_Wl0; }
    else if (i < 2 * L)      { j = i - L;     w = W1[j]; dh = g_Wh1; dl = g_Wl1; }
    else if (i < 2 * L + 64 * KK) { j = i - 2 * L; w = W2[j]; dh = g_Wh2; dl = g_Wl2; }
    else return;
    __nv_bfloat16 hi = __float2bfloat16(w);
    __nv_bfloat16 lo = __float2bfloat16(w - __bfloat162float(hi));
    dh[j] = hi;
    dl[j] = lo;
}

// ================= split x (once): bf16 hi/lo + fp16 shadow =================
__global__ void split_x(const float* __restrict__ x) {
    int i = blockIdx.x * 256 + threadIdx.x;         // float4 index
    if (i >= NN * DD / 4) return;
    float4 v = ((const float4*)x)[i];
    __nv_bfloat162 h0 = __floats2bfloat162_rn(v.x, v.y);
    __nv_bfloat162 h1 = __floats2bfloat162_rn(v.z, v.w);
    __nv_bfloat162 l0 = __floats2bfloat162_rn(v.x - __bfloat162float(h0.x),
                                              v.y - __bfloat162float(h0.y));
    __nv_bfloat162 l1 = __floats2bfloat162_rn(v.z - __bfloat162float(h1.x),
                                              v.w - __bfloat162float(h1.y));
    ((__nv_bfloat162*)g_xhA)[i * 2]     = h0;
    ((__nv_bfloat162*)g_xhA)[i * 2 + 1] = h1;
    ((__nv_bfloat162*)g_xlA)[i * 2]     = l0;
    ((__nv_bfloat162*)g_xlA)[i * 2 + 1] = l1;
    ((__half2*)g_xf16)[i * 2]     = __floats2half2_rn(v.x, v.y);
    ((__half2*)g_xf16)[i * 2 + 1] = __floats2half2_rn(v.z, v.w);
}

// ================= CSR build =================
__global__ void count_kernel(const int* __restrict__ ei) {
    int e4 = blockIdx.x * blockDim.x + threadIdx.x;   // 4 edges per thread
    if (e4 >= NE / 4) return;
    int4 r = ((const int4*)ei)[e4];
    atomicAdd(&g_cnt[r.x], 1);
    atomicAdd(&g_cnt[r.y], 1);
    atomicAdd(&g_cnt[r.z], 1);
    atomicAdd(&g_cnt[r.w], 1);
}

// -- 3-phase multi-block scan --
__global__ void scan_p1() {
    __shared__ int ws[32];
    int i = blockIdx.x * 1024 + threadIdx.x;
    int v = (i < NN) ? g_cnt[i] : 0;
    #pragma unroll
    for (int o = 16; o > 0; o >>= 1) v += __shfl_down_sync(0xffffffffu, v, o);
    if ((threadIdx.x & 31) == 0) ws[threadIdx.x >> 5] = v;
    __syncthreads();
    if (threadIdx.x < 32) {
        int t = ws[threadIdx.x];
        #pragma unroll
        for (int o = 16; o > 0; o >>= 1) t += __shfl_down_sync(0xffffffffu, t, o);
        if (threadIdx.x == 0) g_bsum[blockIdx.x] = t;
    }
}

__global__ void scan_p2() {
    int lane = threadIdx.x & 31;
    int wid  = threadIdx.x >> 5;
    __shared__ int wtot;
    int v = (threadIdx.x < NBLK) ? g_bsum[threadIdx.x] : 0;
    int incl = v;
    #pragma unroll
    for (int o = 1; o < 32; o <<= 1) {
        int t = __shfl_up_sync(0xffffffffu, incl, o);
        if (lane >= o) incl += t;
    }
    if (wid == 0 && lane == 31) wtot = incl;
    __syncthreads();
    int excl = incl - v + (wid ? wtot : 0);
    if (threadIdx.x < NBLK) g_bpre[threadIdx.x] = excl;
    if (threadIdx.x == 0) g_off[NN] = NE;
}

__global__ void scan_p3() {
    __shared__ int ws[32];
    const int tid = threadIdx.x, lane = tid & 31, wid = tid >> 5;
    int i = blockIdx.x * 1024 + tid;
    int v = (i < NN) ? g_cnt[i] : 0;
    int incl = v;
    #pragma unroll
    for (int o = 1; o < 32; o <<= 1) {
        int t = __shfl_up_sync(0xffffffffu, incl, o);
        if (lane >= o) incl += t;
    }
    if (lane == 31) ws[wid] = incl;
    __syncthreads();
    if (wid == 0) {
        int wv = (lane < 32) ? ws[lane] : 0;
        int s = wv;
        #pragma unroll
        for (int o = 1; o < 32; o <<= 1) {
            int t = __shfl_up_sync(0xffffffffu, s, o);
            if (lane >= o) s += t;
        }
        ws[lane] = s - wv;
    }
    __syncthreads();
    int o = g_bpre[blockIdx.x] + ws[wid] + incl - v;
    if (i < NN) { g_off[i] = o; g_cnt[i] = o; }
}

__global__ void fill_kernel(const int* __restrict__ ei, const float* __restrict__ ew) {
    int e4 = blockIdx.x * blockDim.x + threadIdx.x;
    if (e4 >= NE / 4) return;
    int4   r = ((const int4*)ei)[e4];
    int4   c = ((const int4*)(ei + NE))[e4];
    float4 w = ((const float4*)ew)[e4];
    int p;
    p = atomicAdd(&g_cnt[r.x], 1); g_col[p] = c.x; g_wgt[p] = w.x;
    p = atomicAdd(&g_cnt[r.y], 1); g_col[p] = c.y; g_wgt[p] = w.y;
    p = atomicAdd(&g_cnt[r.z], 1); g_col[p] = c.z; g_wgt[p] = w.z;
    p = atomicAdd(&g_cnt[r.w], 1); g_col[p] = c.w; g_wgt[p] = w.w;
}

// ======= aggregation: warp per node (chunked), fp16 gather, MLP=4 ============
__global__ void agg_kernel(const __half* __restrict__ xin, int node0, int ncount) {
    int lw = (blockIdx.x * blockDim.x + threadIdx.x) >> 5;
    if (lw >= ncount) return;
    int gw = node0 + lw;
    const int lane = threadIdx.x & 31;
    const int s = g_off[gw];
    const int e = g_off[gw + 1];
    float4 acc = make_float4(0.f, 0.f, 0.f, 0.f);
    float wsum = 0.f;
    for (int base = s; base < e; base += 32) {
        int nn = min(32, e - base);
        int c = 0; float w = 0.f;
        if (lane < nn) { c = g_col[base + lane]; w = g_wgt[base + lane]; }
        wsum += w;
        int j = 0;
        for (; j + 4 <= nn; j += 4) {
            int cj0 = __shfl_sync(0xffffffffu, c, j);
            int cj1 = __shfl_sync(0xffffffffu, c, j + 1);
            int cj2 = __shfl_sync(0xffffffffu, c, j + 2);
            int cj3 = __shfl_sync(0xffffffffu, c, j + 3);
            float wj0 = __shfl_sync(0xffffffffu, w, j);
            float wj1 = __shfl_sync(0xffffffffu, w, j + 1);
            float wj2 = __shfl_sync(0xffffffffu, w, j + 2);
            float wj3 = __shfl_sync(0xffffffffu, w, j + 3);
            uint2 u0 = *(const uint2*)(xin + (size_t)cj0 * DD + lane * 4);
            uint2 u1 = *(const uint2*)(xin + (size_t)cj1 * DD + lane * 4);
            uint2 u2 = *(const uint2*)(xin + (size_t)cj2 * DD + lane * 4);
            uint2 u3 = *(const uint2*)(xin + (size_t)cj3 * DD + lane * 4);
            {
                float2 a = __half22float2(*(const __half2*)&u0.x);
                float2 b = __half22float2(*(const __half2*)&u0.y);
                acc.x = fmaf(a.x, wj0, acc.x); acc.y = fmaf(a.y, wj0, acc.y);
                acc.z = fmaf(b.x, wj0, acc.z); acc.w = fmaf(b.y, wj0, acc.w);
            }
            {
                float2 a = __half22float2(*(const __half2*)&u1.x);
                float2 b = __half22float2(*(const __half2*)&u1.y);
                acc.x = fmaf(a.x, wj1, acc.x); acc.y = fmaf(a.y, wj1, acc.y);
                acc.z = fmaf(b.x, wj1, acc.z); acc.w = fmaf(b.y, wj1, acc.w);
            }
            {
                float2 a = __half22float2(*(const __half2*)&u2.x);
                float2 b = __half22float2(*(const __half2*)&u2.y);
                acc.x = fmaf(a.x, wj2, acc.x); acc.y = fmaf(a.y, wj2, acc.y);
                acc.z = fmaf(b.x, wj2, acc.z); acc.w = fmaf(b.y, wj2, acc.w);
            }
            {
                float2 a = __half22float2(*(const __half2*)&u3.x);
                float2 b = __half22float2(*(const __half2*)&u3.y);
                acc.x = fmaf(a.x, wj3, acc.x); acc.y = fmaf(a.y, wj3, acc.y);
                acc.z = fmaf(b.x, wj3, acc.z); acc.w = fmaf(b.y, wj3, acc.w);
            }
        }
        for (; j < nn; ++j) {
            int cj = __shfl_sync(0xffffffffu, c, j);
            float wj = __shfl_sync(0xffffffffu, w, j);
            uint2 u = *(const uint2*)(xin + (size_t)cj * DD + lane * 4);
            float2 a = __half22float2(*(const __half2*)&u.x);
            float2 b = __half22float2(*(const __half2*)&u.y);
            acc.x = fmaf(a.x, wj, acc.x); acc.y = fmaf(a.y, wj, acc.y);
            acc.z = fmaf(b.x, wj, acc.z); acc.w = fmaf(b.y, wj, acc.w);
        }
    }
    #pragma unroll
    for (int o = 16; o > 0; o >>= 1) wsum += __shfl_xor_sync(0xffffffffu, wsum, o);
    float invd = 1.0f / fmaxf(wsum, 1.0f);
    float v0 = acc.x * invd, v1 = acc.y * invd, v2 = acc.z * invd, v3 = acc.w * invd;
    __nv_bfloat162 h01 = __floats2bfloat162_rn(v0, v1);
    __nv_bfloat162 h23 = __floats2bfloat162_rn(v2, v3);
    __nv_bfloat162 l01 = __floats2bfloat162_rn(v0 - __bfloat162float(h01.x),
                                               v1 - __bfloat162float(h01.y));
    __nv_bfloat162 l23 = __floats2bfloat162_rn(v2 - __bfloat162float(h23.x),
                                               v3 - __bfloat162float(h23.y));
    __nv_bfloat162* oh = (__nv_bfloat162*)g_ah + (size_t)gw * 64 + lane * 2;
    __nv_bfloat162* ol = (__nv_bfloat162*)g_al + (size_t)gw * 64 + lane * 2;
    oh[0] = h01; oh[1] = h23;
    ol[0] = l01; ol[1] = l23;
}

// ================= HMMA GEMM: out = [X|Agg] @ W^T + b (chunked) ==============
// BK=32, 8 K-tiles, double-buffered; stage = 40KB (BN=128) -> 2 CTAs/SM.
template <int BN, bool RELU, bool SPLIT>
__global__ void __launch_bounds__(256, 2) tgemm_kernel(
    const __nv_bfloat16* __restrict__ Xh, const __nv_bfloat16* __restrict__ Xl,
    const __nv_bfloat16* __restrict__ Wh, const __nv_bfloat16* __restrict__ Wl,
    const float* __restrict__ bias,
    float* __restrict__ outF,
    __nv_bfloat16* __restrict__ outHh, __nv_bfloat16* __restrict__ outHl,
    __half* __restrict__ outH16, int blk0)
{
    extern __shared__ __align__(16) char smem[];
    constexpr int PADB  = 80;                  // 32 bf16 = 64B row + 16B pad
    constexpr int ASZ   = 128 * PADB;          // 10240
    constexpr int BSZ   = BN * PADB;
    constexpr int STAGE = 2 * ASZ + 2 * BSZ;
    constexpr int WARP_N = BN / 4;
    constexpr int NFRAG  = WARP_N / 8;
    constexpr int NLB    = NFRAG / 2;
    constexpr int BLOADS = (BN * 4) / 256;     // B 16B-chunks per thread (2 or 1)

    const int tid  = threadIdx.x;
    const int lane = tid & 31;
    const int wid  = tid >> 5;
    const int wm   = wid >> 2;
    const int wn   = wid & 3;
    const int m0   = (blk0 + blockIdx.x) * 128;

    const uint32_t sbase = smem_u32(smem);
    const uint32_t offA = (uint32_t)((wm * 64 + (lane & 15)) * PADB + (lane >> 4) * 16);
    const uint32_t offB = (uint32_t)((wn * WARP_N + (lane & 7) + ((lane >> 4) << 3)) * PADB
                                     + (lane & 8) * 2);

    float acc[4][NFRAG][4];
    #pragma unroll
    for (int i = 0; i < 4; ++i)
        #pragma unroll
        for (int j = 0; j < NFRAG; ++j)
            #pragma unroll
            for (int q = 0; q < 4; ++q) acc[i][j][q] = 0.f;

    // tile t covers global k [t*32, t*32+32): t<4 from X, t>=4 from Agg
    auto issue = [&](int t, int b) {
        const uint32_t st = sbase + b * STAGE;
        const __nv_bfloat16* axh = (t < 4) ? Xh : g_ah;
        const __nv_bfloat16* axl = (t < 4) ? Xl : g_al;
        const int colb = (t & 3) * 32;
        #pragma unroll
        for (int i = 0; i < 2; ++i) {
            int idx = tid + i * 256;            // 0..511: 128 rows x 4 chunks
            int row = idx >> 2, ch = idx & 3;
            int gr = m0 + row;
            int ok = (gr < NN) ? 16 : 0;
            int grc = (gr < NN) ? gr : 0;
            size_t go = (size_t)grc * DD + colb + ch * 8;
            uint32_t sa = (uint32_t)(row * PADB + ch * 16);
            cpa16(st + sa,        axh + go, ok);
            cpa16(st + ASZ + sa,  axl + go, ok);
        }
        #pragma unroll
        for (int i = 0; i < BLOADS; ++i) {
            int idx = tid + i * 256;            // BN rows x 4 chunks
            int row = idx >> 2, ch = idx & 3;
            size_t go = (size_t)row * KK + t * 32 + ch * 8;
            uint32_t sa = (uint32_t)(row * PADB + ch * 16);
            cpa16(st + 2 * ASZ + sa,       Wh + go, 16);
            cpa16(st + 2 * ASZ + BSZ + sa, Wl + go, 16);
        }
        CPA_COMMIT();
    };

    auto compute = [&](int b) {
        const uint32_t st  = sbase + b * STAGE;
        const uint32_t pAh = st + offA;
        const uint32_t pAl = st + ASZ + offA;
        const uint32_t pBh = st + 2 * ASZ + offB;
        const uint32_t pBl = st + 2 * ASZ + BSZ + offB;
        #pragma unroll
        for (int kk = 0; kk < 2; ++kk) {
            const int kb = kk * 32;             // 16 bf16 = 32 bytes per step
            uint32_t a[4][4];
            #pragma unroll
            for (int mi = 0; mi < 4; ++mi) ldsm4(a[mi], pAh + mi * (16 * PADB) + kb);
            uint32_t bh[NLB][4];
            #pragma unroll
            for (int p = 0; p < NLB; ++p) ldsm4(bh[p], pBh + p * (16 * PADB) + kb);
            #pragma unroll
            for (int mi = 0; mi < 4; ++mi)
                #pragma unroll
                for (int p = 0; p < NLB; ++p) {
                    mma16816(acc[mi][p * 2],     a[mi], bh[p][0], bh[p][1]);
                    mma16816(acc[mi][p * 2 + 1], a[mi], bh[p][2], bh[p][3]);
                }
            uint32_t bl[NLB][4];
            #pragma unroll
            for (int p = 0; p < NLB; ++p) ldsm4(bl[p], pBl + p * (16 * PADB) + kb);
            #pragma unroll
            for (int mi = 0; mi < 4; ++mi)
                #pragma unroll
                for (int p = 0; p < NLB; ++p) {
                    mma16816(acc[mi][p * 2],     a[mi], bl[p][0], bl[p][1]);
                    mma16816(acc[mi][p * 2 + 1], a[mi], bl[p][2], bl[p][3]);
                }
            #pragma unroll
            for (int mi = 0; mi < 4; ++mi) ldsm4(a[mi], pAl + mi * (16 * PADB) + kb);
            #pragma unroll
            for (int mi = 0; mi < 4; ++mi)
                #pragma unroll
                for (int p = 0; p < NLB; ++p) {
                    mma16816(acc[mi][p * 2],     a[mi], bh[p][0], bh[p][1]);
                    mma16816(acc[mi][p * 2 + 1], a[mi], bh[p][2], bh[p][3]);
                }
        }
    };

    issue(0, 0);
    issue(1, 1);
    #pragma unroll 1
    for (int t = 0; t < 8; ++t) {
        if (t < 7) asm volatile("cp.async.wait_group 1;" ::: "memory");
        else       asm volatile("cp.async.wait_group 0;" ::: "memory");
        __syncthreads();
        compute(t & 1);
        __syncthreads();
        if (t < 6) issue(t + 2, t & 1);
    }

    #pragma unroll
    for (int mi = 0; mi < 4; ++mi) {
        int r0 = m0 + wm * 64 + mi * 16 + (lane >> 2);
        #pragma unroll
        for (int nj = 0; nj < NFRAG; ++nj) {
            int c = wn * WARP_N + nj * 8 + (lane & 3) * 2;
            float bb0 = __ldg(&bias[c]);
            float bb1 = __ldg(&bias[c + 1]);
            const float* d = acc[mi][nj];
            float v00 = d[0] + bb0, v01 = d[1] + bb1;
            float v10 = d[2] + bb0, v11 = d[3] + bb1;
            if (RELU) {
                v00 = fmaxf(v00, 0.f); v01 = fmaxf(v01, 0.f);
                v10 = fmaxf(v10, 0.f); v11 = fmaxf(v11, 0.f);
            }
            if (r0 < NN) {
                if (SPLIT) {
                    __nv_bfloat162 H = __floats2bfloat162_rn(v00, v01);
                    __nv_bfloat162 L = __floats2bfloat162_rn(v00 - __bfloat162float(H.x),
                                                             v01 - __bfloat162float(H.y));
                    *(__nv_bfloat162*)(outHh + (size_t)r0 * DD + c) = H;
                    *(__nv_bfloat162*)(outHl + (size_t)r0 * DD + c) = L;
                    *(__half2*)(outH16 + (size_t)r0 * DD + c) = __floats2half2_rn(v00, v01);
                } else {
                    *(float2*)(outF + (size_t)r0 * BN + c) = make_float2(v00, v01);
                }
            }
            if (r0 + 8 < NN) {
                if (SPLIT) {
                    __nv_bfloat162 H = __floats2bfloat162_rn(v10, v11);
                    __nv_bfloat162 L = __floats2bfloat162_rn(v10 - __bfloat162float(H.x),
                                                             v11 - __bfloat162float(H.y));
                    *(__nv_bfloat162*)(outHh + (size_t)(r0 + 8) * DD + c) = H;
                    *(__nv_bfloat162*)(outHl + (size_t)(r0 + 8) * DD + c) = L;
                    *(__half2*)(outH16 + (size_t)(r0 + 8) * DD + c) = __floats2half2_rn(v10, v11);
                } else {
                    *(float2*)(outF + (size_t)(r0 + 8) * BN + c) = make_float2(v10, v11);
                }
            }
        }
    }
}

// ================= launch =================
extern "C" void kernel_launch(void* const* d_in, const int* in_sizes, int n_in,
                              void* d_out, int out_size) {
    (void)in_sizes; (void)n_in; (void)out_size;
    const float* x  = (const float*)d_in[0];
    const int*   ei = (const int*)d_in[1];
    const float* ew = (const float*)d_in[2];
    const float* W0 = (const float*)d_in[3];
    const float* b0 = (const float*)d_in[4];
    const float* W1 = (const float*)d_in[5];
    const float* b1 = (const float*)d_in[6];
    const float* W2 = (const float*)d_in[7];
    const float* b2 = (const float*)d_in[8];
    float* out = (float*)d_out;

    void *p_cnt, *p_xf16, *p_hf16;
    void *p_xhA, *p_xlA, *p_xhB, *p_xlB;
    void *p_wh0, *p_wl0, *p_wh1, *p_wl1, *p_wh2, *p_wl2;
    cudaGetSymbolAddress(&p_cnt,  g_cnt);
    cudaGetSymbolAddress(&p_xf16, g_xf16);
    cudaGetSymbolAddress(&p_hf16, g_hf16);
    cudaGetSymbolAddress(&p_xhA, g_xhA);
    cudaGetSymbolAddress(&p_xlA, g_xlA);
    cudaGetSymbolAddress(&p_xhB, g_xhB);
    cudaGetSymbolAddress(&p_xlB, g_xlB);
    cudaGetSymbolAddress(&p_wh0, g_Wh0);
    cudaGetSymbolAddress(&p_wl0, g_Wl0);
    cudaGetSymbolAddress(&p_wh1, g_Wh1);
    cudaGetSymbolAddress(&p_wl1, g_Wl1);
    cudaGetSymbolAddress(&p_wh2, g_Wh2);
    cudaGetSymbolAddress(&p_wl2, g_Wl2);

    const int SMEM128 = 2 * (2 * 128 * 80 + 2 * 128 * 80);   // 81920
    const int SMEM64  = 2 * (2 * 128 * 80 + 2 * 64 * 80);    // 61440
    cudaFuncSetAttribute(tgemm_kernel<128, true, true>,
                         cudaFuncAttributeMaxDynamicSharedMemorySize, SMEM128);
    cudaFuncSetAttribute(tgemm_kernel<64, false, false>,
                         cudaFuncAttributeMaxDynamicSharedMemorySize, SMEM64);

    // streams + events (created once, outside capture; reused inside capture)
    static cudaStream_t s1 = nullptr;
    static cudaEvent_t evs[16];
    if (s1 == nullptr) {
        cudaStreamCreateWithFlags(&s1, cudaStreamNonBlocking);
        for (int i = 0; i < 16; ++i)
            cudaEventCreateWithFlags(&evs[i], cudaEventDisableTiming);
    }

    cudaMemsetAsync(p_cnt, 0, NN * sizeof(int), 0);

    // fork: CSR build chain on s1, feature prep on main stream
    cudaEventRecord(evs[0], 0);
    cudaStreamWaitEvent(s1, evs[0], 0);
    count_kernel<<<(NE / 4 + 255) / 256, 256, 0, s1>>>(ei);
    scan_p1<<<NBLK, 1024, 0, s1>>>();
    scan_p2<<<1, 64, 0, s1>>>();
    scan_p3<<<NBLK, 1024, 0, s1>>>();
    fill_kernel<<<(NE / 4 + 255) / 256, 256, 0, s1>>>(ei, ew);
    cudaEventRecord(evs[1], s1);

    const int totW = 2 * 128 * KK + 64 * KK;
    prep_W<<<(totW + 255) / 256, 256>>>(W0, W1, W2);
    split_x<<<(NN * DD / 4 + 255) / 256, 256>>>(x);

    cudaStreamWaitEvent(0, evs[1], 0);   // join before aggregation

    // ---- chunked layer schedule: agg on main stream, gemm on s1 ----
    const int GB   = 391;                 // total gemm blocks (ceil 50000/128)
    const int GB0  = 196, GB1 = GB - GB0; // chunk block counts
    const int N0   = GB0 * 128;           // 25088 rows in chunk 0
    const int N1   = NN - N0;             // 24912 rows in chunk 1
    const int AB0  = (N0 + 7) / 8;
    const int AB1  = (N1 + 7) / 8;

    const __nv_bfloat16* Xh[3] = {(const __nv_bfloat16*)p_xhA, (const __nv_bfloat16*)p_xhB, (const __nv_bfloat16*)p_xhA};
    const __nv_bfloat16* Xl[3] = {(const __nv_bfloat16*)p_xlA, (const __nv_bfloat16*)p_xlB, (const __nv_bfloat16*)p_xlA};
    const __half* Ain[3] = {(const __half*)p_xf16, (const __half*)p_hf16, (const __half*)p_hf16};

    // layer 0
    agg_kernel<<<AB0, 256>>>(Ain[0], 0, N0);
    cudaEventRecord(evs[2], 0);
    agg_kernel<<<AB1, 256>>>(Ain[0], N0, N1);
    cudaEventRecord(evs[3], 0);
    cudaStreamWaitEvent(s1, evs[2], 0);
    tgemm_kernel<128, true, true><<<GB0, 256, SMEM128, s1>>>(
        Xh[0], Xl[0], (const __nv_bfloat16*)p_wh0, (const __nv_bfloat16*)p_wl0,
        b0, nullptr, (__nv_bfloat16*)p_xhB, (__nv_bfloat16*)p_xlB, (__half*)p_hf16, 0);
    cudaStreamWaitEvent(s1, evs[3], 0);
    tgemm_kernel<128, true, true><<<GB1, 256, SMEM128, s1>>>(
        Xh[0], Xl[0], (const __nv_bfloat16*)p_wh0, (const __nv_bfloat16*)p_wl0,
        b0, nullptr, (__nv_bfloat16*)p_xhB, (__nv_bfloat16*)p_xlB, (__half*)p_hf16, GB0);
    cudaEventRecord(evs[4], s1);
    cudaStreamWaitEvent(0, evs[4], 0);

    // layer 1
    agg_kernel<<<AB0, 256>>>(Ain[1], 0, N0);
    cudaEventRecord(evs[5], 0);
    agg_kernel<<<AB1, 256>>>(Ain[1], N0, N1);
    cudaEventRecord(evs[6], 0);
    cudaStreamWaitEvent(s1, evs[5], 0);
    tgemm_kernel<128, true, true><<<GB0, 256, SMEM128, s1>>>(
        Xh[1], Xl[1], (const __nv_bfloat16*)p_wh1, (const __nv_bfloat16*)p_wl1,
        b1, nullptr, (__nv_bfloat16*)p_xhA, (__nv_bfloat16*)p_xlA, (__half*)p_hf16, 0);
    cudaStreamWaitEvent(s1, evs[6], 0);
    tgemm_kernel<128, true, true><<<GB1, 256, SMEM128, s1>>>(
        Xh[1], Xl[1], (const __nv_bfloat16*)p_wh1, (const __nv_bfloat16*)p_wl1,
        b1, nullptr, (__nv_bfloat16*)p_xhA, (__nv_bfloat16*)p_xlA, (__half*)p_hf16, GB0);
    cudaEventRecord(evs[7], s1);
    cudaStreamWaitEvent(0, evs[7], 0);

    // layer 2
    agg_kernel<<<AB0, 256>>>(Ain[2], 0, N0);
    cudaEventRecord(evs[8], 0);
    agg_kernel<<<AB1, 256>>>(Ain[2], N0, N1);
    cudaEventRecord(evs[9], 0);
    cudaStreamWaitEvent(s1, evs[8], 0);
    tgemm_kernel<64, false, false><<<GB0, 256, SMEM64, s1>>>(
        Xh[2], Xl[2], (const __nv_bfloat16*)p_wh2, (const __nv_bfloat16*)p_wl2,
        b2, out, nullptr, nullptr, nullptr, 0);
    cudaStreamWaitEvent(s1, evs[9], 0);
    tgemm_kernel<64, false, false><<<GB1, 256, SMEM64, s1>>>(
        Xh[2], Xl[2], (const __nv_bfloat16*)p_wh2, (const __nv_bfloat16*)p_wl2,
        b2, out, nullptr, nullptr, nullptr, GB0);
    cudaEventRecord(evs[10], s1);
    cudaStreamWaitEvent(0, evs[10], 0);
}

// round 12
// speedup vs baseline: 1.1685x; 1.1685x over previous
#include <cuda_runtime.h>
#include <cuda_bf16.h>
#include <cuda_fp16.h>
#include <cstdint>
#include <cstddef>

#define NN   50000
#define NE   800000
#define DD   128
#define KK   256
#define NBLK 49          // ceil(NN/1024)

// ================= low-level helpers =================
__device__ __forceinline__ uint32_t smem_u32(const void* p) {
    uint32_t a;
    asm("{ .reg .u64 t; cvta.to.shared.u64 t, %1; cvt.u32.u64 %0, t; }" : "=r"(a) : "l"(p));
    return a;
}
__device__ __forceinline__ void ldsm4(uint32_t* r, uint32_t addr) {
    asm volatile("ldmatrix.sync.aligned.m8n8.x4.shared.b16 {%0,%1,%2,%3}, [%4];"
                 : "=r"(r[0]), "=r"(r[1]), "=r"(r[2]), "=r"(r[3]) : "r"(addr));
}
__device__ __forceinline__ void mma16816(float* d, const uint32_t* a, uint32_t b0, uint32_t b1) {
    asm volatile(
        "mma.sync.aligned.m16n8k16.row.col.f32.bf16.bf16.f32 "
        "{%0,%1,%2,%3}, {%4,%5,%6,%7}, {%8,%9}, {%0,%1,%2,%3};"
        : "+f"(d[0]), "+f"(d[1]), "+f"(d[2]), "+f"(d[3])
        : "r"(a[0]), "r"(a[1]), "r"(a[2]), "r"(a[3]), "r"(b0), "r"(b1));
}
__device__ __forceinline__ void cpa16(uint32_t dst, const void* src, int sz) {
    asm volatile("cp.async.cg.shared.global [%0], [%1], 16, %2;"
                 :: "r"(dst), "l"(src), "r"(sz));
}
#define CPA_COMMIT() asm volatile("cp.async.commit_group;" ::: "memory")

// ================= device scratch =================
__device__ int   g_cnt[NN];          // zeroed by agg (prev run); static-zero on run 1
__device__ int   g_off[NN + 1];
__device__ volatile int g_bsumV[NBLK];
__device__ volatile int g_bflag[NBLK];   // reset by fill (after scan_lb completes)
__device__ int   g_col[NE];
__device__ float g_wgt[NE];
__device__ __half g_xf16[NN * DD];
__device__ __half g_hf16[NN * DD];
__device__ __nv_bfloat16 g_xhA[NN * DD], g_xlA[NN * DD];
__device__ __nv_bfloat16 g_xhB[NN * DD], g_xlB[NN * DD];
__device__ __nv_bfloat16 g_ah[NN * DD],  g_al[NN * DD];
__device__ __nv_bfloat16 g_Wh0[128 * KK], g_Wl0[128 * KK];
__device__ __nv_bfloat16 g_Wh1[128 * KK], g_Wl1[128 * KK];
__device__ __nv_bfloat16 g_Wh2[64 * KK],  g_Wl2[64 * KK];

// ========== prep_all: split x (bf16 hi/lo + fp16) AND split weights ==========
__global__ void prep_all(const float* __restrict__ x,
                         const float* __restrict__ W0,
                         const float* __restrict__ W1,
                         const float* __restrict__ W2) {
    const int XQ = NN * DD / 4;
    int i = blockIdx.x * 256 + threadIdx.x;
    if (i < XQ) {
        float4 v = ((const float4*)x)[i];
        __nv_bfloat162 h0 = __floats2bfloat162_rn(v.x, v.y);
        __nv_bfloat162 h1 = __floats2bfloat162_rn(v.z, v.w);
        __nv_bfloat162 l0 = __floats2bfloat162_rn(v.x - __bfloat162float(h0.x),
                                                  v.y - __bfloat162float(h0.y));
        __nv_bfloat162 l1 = __floats2bfloat162_rn(v.z - __bfloat162float(h1.x),
                                                  v.w - __bfloat162float(h1.y));
        ((__nv_bfloat162*)g_xhA)[i * 2]     = h0;
        ((__nv_bfloat162*)g_xhA)[i * 2 + 1] = h1;
        ((__nv_bfloat162*)g_xlA)[i * 2]     = l0;
        ((__nv_bfloat162*)g_xlA)[i * 2 + 1] = l1;
        ((__half2*)g_xf16)[i * 2]     = __floats2half2_rn(v.x, v.y);
        ((__half2*)g_xf16)[i * 2 + 1] = __floats2half2_rn(v.z, v.w);
        return;
    }
    int k = i - XQ;
    const int L = 128 * KK;
    float w; __nv_bfloat16 *dh, *dl; int j;
    if (k < L)                    { j = k;         w = W0[j]; dh = g_Wh0; dl = g_Wl0; }
    else if (k < 2 * L)           { j = k - L;     w = W1[j]; dh = g_Wh1; dl = g_Wl1; }
    else if (k < 2 * L + 64 * KK) { j = k - 2 * L; w = W2[j]; dh = g_Wh2; dl = g_Wl2; }
    else return;
    __nv_bfloat16 hi = __float2bfloat16(w);
    __nv_bfloat16 lo = __float2bfloat16(w - __bfloat162float(hi));
    dh[j] = hi;
    dl[j] = lo;
}

// ================= CSR build =================
__global__ void count_kernel(const int* __restrict__ ei) {
    int e4 = blockIdx.x * blockDim.x + threadIdx.x;
    if (e4 >= NE / 4) return;
    int4 r = ((const int4*)ei)[e4];
    atomicAdd(&g_cnt[r.x], 1);
    atomicAdd(&g_cnt[r.y], 1);
    atomicAdd(&g_cnt[r.z], 1);
    atomicAdd(&g_cnt[r.w], 1);
}

// single-kernel decoupled-lookback exclusive scan (49 blocks, all resident)
__global__ void scan_lb() {
    __shared__ int ws[32];
    __shared__ int s_prefix;
    const int tid = threadIdx.x, lane = tid & 31, wid = tid >> 5;
    const int b = blockIdx.x;
    int i = b * 1024 + tid;
    int v = (i < NN) ? g_cnt[i] : 0;

    // warp inclusive scan
    int incl = v;
    #pragma unroll
    for (int o = 1; o < 32; o <<= 1) {
        int t = __shfl_up_sync(0xffffffffu, incl, o);
        if (lane >= o) incl += t;
    }
    if (lane == 31) ws[wid] = incl;
    __syncthreads();

    if (wid == 0) {
        int wv = ws[lane];
        int s = wv;
        #pragma unroll
        for (int o = 1; o < 32; o <<= 1) {
            int t = __shfl_up_sync(0xffffffffu, s, o);
            if (lane >= o) s += t;
        }
        if (lane == 31) {                       // publish block total
            g_bsumV[b] = s;
            __threadfence();
            g_bflag[b] = 1;
        }
        int excl = s - wv;                      // exclusive warp offsets
        // lookback: lanes poll predecessor flags in parallel
        int p = 0;
        for (int q = lane; q < b; q += 32) {
            while (g_bflag[q] == 0) { }
            p += g_bsumV[q];
        }
        #pragma unroll
        for (int o = 16; o > 0; o >>= 1) p += __shfl_xor_sync(0xffffffffu, p, o);
        if (lane == 0) s_prefix = p;
        ws[lane] = excl;                        // safe: all reads of old ws done pre-sync
    }
    __syncthreads();

    int o = s_prefix + ws[wid] + incl - v;
    if (i < NN) { g_off[i] = o; g_cnt[i] = o; }
    if (b == 0 && tid == 0) g_off[NN] = NE;
}

__global__ void fill_kernel(const int* __restrict__ ei, const float* __restrict__ ew) {
    int e4 = blockIdx.x * blockDim.x + threadIdx.x;
    if (e4 < NBLK) g_bflag[e4] = 0;            // reset lookback flags for next run
    if (e4 >= NE / 4) return;
    int4   r = ((const int4*)ei)[e4];
    int4   c = ((const int4*)(ei + NE))[e4];
    float4 w = ((const float4*)ew)[e4];
    int p;
    p = atomicAdd(&g_cnt[r.x], 1); g_col[p] = c.x; g_wgt[p] = w.x;
    p = atomicAdd(&g_cnt[r.y], 1); g_col[p] = c.y; g_wgt[p] = w.y;
    p = atomicAdd(&g_cnt[r.z], 1); g_col[p] = c.z; g_wgt[p] = w.z;
    p = atomicAdd(&g_cnt[r.w], 1); g_col[p] = c.w; g_wgt[p] = w.w;
}

// ======= aggregation: warp per node, fp16 gather, MLP=4; also zeroes g_cnt ====
__global__ void agg_kernel(const __half* __restrict__ xin) {
    int gt = blockIdx.x * blockDim.x + threadIdx.x;
    if (gt < NN) g_cnt[gt] = 0;                // reset histogram for next run
    int gw = gt >> 5;
    if (gw >= NN) return;
    const int lane = threadIdx.x & 31;
    const int s = g_off[gw];
    const int e = g_off[gw + 1];
    float4 acc = make_float4(0.f, 0.f, 0.f, 0.f);
    float wsum = 0.f;
    for (int base = s; base < e; base += 32) {
        int nn = min(32, e - base);
        int c = 0; float w = 0.f;
        if (lane < nn) { c = g_col[base + lane]; w = g_wgt[base + lane]; }
        wsum += w;
        int j = 0;
        for (; j + 4 <= nn; j += 4) {
            int cj0 = __shfl_sync(0xffffffffu, c, j);
            int cj1 = __shfl_sync(0xffffffffu, c, j + 1);
            int cj2 = __shfl_sync(0xffffffffu, c, j + 2);
            int cj3 = __shfl_sync(0xffffffffu, c, j + 3);
            float wj0 = __shfl_sync(0xffffffffu, w, j);
            float wj1 = __shfl_sync(0xffffffffu, w, j + 1);
            float wj2 = __shfl_sync(0xffffffffu, w, j + 2);
            float wj3 = __shfl_sync(0xffffffffu, w, j + 3);
            uint2 u0 = *(const uint2*)(xin + (size_t)cj0 * DD + lane * 4);
            uint2 u1 = *(const uint2*)(xin + (size_t)cj1 * DD + lane * 4);
            uint2 u2 = *(const uint2*)(xin + (size_t)cj2 * DD + lane * 4);
            uint2 u3 = *(const uint2*)(xin + (size_t)cj3 * DD + lane * 4);
            {
                float2 a = __half22float2(*(const __half2*)&u0.x);
                float2 b = __half22float2(*(const __half2*)&u0.y);
                acc.x = fmaf(a.x, wj0, acc.x); acc.y = fmaf(a.y, wj0, acc.y);
                acc.z = fmaf(b.x, wj0, acc.z); acc.w = fmaf(b.y, wj0, acc.w);
            }
            {
                float2 a = __half22float2(*(const __half2*)&u1.x);
                float2 b = __half22float2(*(const __half2*)&u1.y);
                acc.x = fmaf(a.x, wj1, acc.x); acc.y = fmaf(a.y, wj1, acc.y);
                acc.z = fmaf(b.x, wj1, acc.z); acc.w = fmaf(b.y, wj1, acc.w);
            }
            {
                float2 a = __half22float2(*(const __half2*)&u2.x);
                float2 b = __half22float2(*(const __half2*)&u2.y);
                acc.x = fmaf(a.x, wj2, acc.x); acc.y = fmaf(a.y, wj2, acc.y);
                acc.z = fmaf(b.x, wj2, acc.z); acc.w = fmaf(b.y, wj2, acc.w);
            }
            {
                float2 a = __half22float2(*(const __half2*)&u3.x);
                float2 b = __half22float2(*(const __half2*)&u3.y);
                acc.x = fmaf(a.x, wj3, acc.x); acc.y = fmaf(a.y, wj3, acc.y);
                acc.z = fmaf(b.x, wj3, acc.z); acc.w = fmaf(b.y, wj3, acc.w);
            }
        }
        for (; j < nn; ++j) {
            int cj = __shfl_sync(0xffffffffu, c, j);
            float wj = __shfl_sync(0xffffffffu, w, j);
            uint2 u = *(const uint2*)(xin + (size_t)cj * DD + lane * 4);
            float2 a = __half22float2(*(const __half2*)&u.x);
            float2 b = __half22float2(*(const __half2*)&u.y);
            acc.x = fmaf(a.x, wj, acc.x); acc.y = fmaf(a.y, wj, acc.y);
            acc.z = fmaf(b.x, wj, acc.z); acc.w = fmaf(b.y, wj, acc.w);
        }
    }
    #pragma unroll
    for (int o = 16; o > 0; o >>= 1) wsum += __shfl_xor_sync(0xffffffffu, wsum, o);
    float invd = 1.0f / fmaxf(wsum, 1.0f);
    float v0 = acc.x * invd, v1 = acc.y * invd, v2 = acc.z * invd, v3 = acc.w * invd;
    __nv_bfloat162 h01 = __floats2bfloat162_rn(v0, v1);
    __nv_bfloat162 h23 = __floats2bfloat162_rn(v2, v3);
    __nv_bfloat162 l01 = __floats2bfloat162_rn(v0 - __bfloat162float(h01.x),
                                               v1 - __bfloat162float(h01.y));
    __nv_bfloat162 l23 = __floats2bfloat162_rn(v2 - __bfloat162float(h23.x),
                                               v3 - __bfloat162float(h23.y));
    __nv_bfloat162* oh = (__nv_bfloat162*)g_ah + (size_t)gw * 64 + lane * 2;
    __nv_bfloat162* ol = (__nv_bfloat162*)g_al + (size_t)gw * 64 + lane * 2;
    oh[0] = h01; oh[1] = h23;
    ol[0] = l01; ol[1] = l23;
}

// ================= HMMA GEMM: out = [X|Agg] @ W^T + b =================
// BK=32, 8 K-tiles, double-buffered; stage = 40KB (BN=128) -> 2 CTAs/SM.
template <int BN, bool RELU, bool SPLIT>
__global__ void __launch_bounds__(256, 2) tgemm_kernel(
    const __nv_bfloat16* __restrict__ Xh, const __nv_bfloat16* __restrict__ Xl,
    const __nv_bfloat16* __restrict__ Wh, const __nv_bfloat16* __restrict__ Wl,
    const float* __restrict__ bias,
    float* __restrict__ outF,
    __nv_bfloat16* __restrict__ outHh, __nv_bfloat16* __restrict__ outHl,
    __half* __restrict__ outH16)
{
    extern __shared__ __align__(16) char smem[];
    constexpr int PADB  = 80;
    constexpr int ASZ   = 128 * PADB;
    constexpr int BSZ   = BN * PADB;
    constexpr int STAGE = 2 * ASZ + 2 * BSZ;
    constexpr int WARP_N = BN / 4;
    constexpr int NFRAG  = WARP_N / 8;
    constexpr int NLB    = NFRAG / 2;
    constexpr int BLOADS = (BN * 4) / 256;

    const int tid  = threadIdx.x;
    const int lane = tid & 31;
    const int wid  = tid >> 5;
    const int wm   = wid >> 2;
    const int wn   = wid & 3;
    const int m0   = blockIdx.x * 128;

    const uint32_t sbase = smem_u32(smem);
    const uint32_t offA = (uint32_t)((wm * 64 + (lane & 15)) * PADB + (lane >> 4) * 16);
    const uint32_t offB = (uint32_t)((wn * WARP_N + (lane & 7) + ((lane >> 4) << 3)) * PADB
                                     + (lane & 8) * 2);

    float acc[4][NFRAG][4];
    #pragma unroll
    for (int i = 0; i < 4; ++i)
        #pragma unroll
        for (int j = 0; j < NFRAG; ++j)
            #pragma unroll
            for (int q = 0; q < 4; ++q) acc[i][j][q] = 0.f;

    auto issue = [&](int t, int b) {
        const uint32_t st = sbase + b * STAGE;
        const __nv_bfloat16* axh = (t < 4) ? Xh : g_ah;
        const __nv_bfloat16* axl = (t < 4) ? Xl : g_al;
        const int colb = (t & 3) * 32;
        #pragma unroll
        for (int i = 0; i < 2; ++i) {
            int idx = tid + i * 256;
            int row = idx >> 2, ch = idx & 3;
            int gr = m0 + row;
            int ok = (gr < NN) ? 16 : 0;
            int grc = (gr < NN) ? gr : 0;
            size_t go = (size_t)grc * DD + colb + ch * 8;
            uint32_t sa = (uint32_t)(row * PADB + ch * 16);
            cpa16(st + sa,        axh + go, ok);
            cpa16(st + ASZ + sa,  axl + go, ok);
        }
        #pragma unroll
        for (int i = 0; i < BLOADS; ++i) {
            int idx = tid + i * 256;
            int row = idx >> 2, ch = idx & 3;
            size_t go = (size_t)row * KK + t * 32 + ch * 8;
            uint32_t sa = (uint32_t)(row * PADB + ch * 16);
            cpa16(st + 2 * ASZ + sa,       Wh + go, 16);
            cpa16(st + 2 * ASZ + BSZ + sa, Wl + go, 16);
        }
        CPA_COMMIT();
    };

    auto compute = [&](int b) {
        const uint32_t st  = sbase + b * STAGE;
        const uint32_t pAh = st + offA;
        const uint32_t pAl = st + ASZ + offA;
        const uint32_t pBh = st + 2 * ASZ + offB;
        const uint32_t pBl = st + 2 * ASZ + BSZ + offB;
        #pragma unroll
        for (int kk = 0; kk < 2; ++kk) {
            const int kb = kk * 32;
            uint32_t a[4][4];
            #pragma unroll
            for (int mi = 0; mi < 4; ++mi) ldsm4(a[mi], pAh + mi * (16 * PADB) + kb);
            uint32_t bh[NLB][4];
            #pragma unroll
            for (int p = 0; p < NLB; ++p) ldsm4(bh[p], pBh + p * (16 * PADB) + kb);
            #pragma unroll
            for (int mi = 0; mi < 4; ++mi)
                #pragma unroll
                for (int p = 0; p < NLB; ++p) {
                    mma16816(acc[mi][p * 2],     a[mi], bh[p][0], bh[p][1]);
                    mma16816(acc[mi][p * 2 + 1], a[mi], bh[p][2], bh[p][3]);
                }
            uint32_t bl[NLB][4];
            #pragma unroll
            for (int p = 0; p < NLB; ++p) ldsm4(bl[p], pBl + p * (16 * PADB) + kb);
            #pragma unroll
            for (int mi = 0; mi < 4; ++mi)
                #pragma unroll
                for (int p = 0; p < NLB; ++p) {
                    mma16816(acc[mi][p * 2],     a[mi], bl[p][0], bl[p][1]);
                    mma16816(acc[mi][p * 2 + 1], a[mi], bl[p][2], bl[p][3]);
                }
            #pragma unroll
            for (int mi = 0; mi < 4; ++mi) ldsm4(a[mi], pAl + mi * (16 * PADB) + kb);
            #pragma unroll
            for (int mi = 0; mi < 4; ++mi)
                #pragma unroll
                for (int p = 0; p < NLB; ++p) {
                    mma16816(acc[mi][p * 2],     a[mi], bh[p][0], bh[p][1]);
                    mma16816(acc[mi][p * 2 + 1], a[mi], bh[p][2], bh[p][3]);
                }
        }
    };

    issue(0, 0);
    issue(1, 1);
    #pragma unroll 1
    for (int t = 0; t < 8; ++t) {
        if (t < 7) asm volatile("cp.async.wait_group 1;" ::: "memory");
        else       asm volatile("cp.async.wait_group 0;" ::: "memory");
        __syncthreads();
        compute(t & 1);
        __syncthreads();
        if (t < 6) issue(t + 2, t & 1);
    }

    #pragma unroll
    for (int mi = 0; mi < 4; ++mi) {
        int r0 = m0 + wm * 64 + mi * 16 + (lane >> 2);
        #pragma unroll
        for (int nj = 0; nj < NFRAG; ++nj) {
            int c = wn * WARP_N + nj * 8 + (lane & 3) * 2;
            float bb0 = __ldg(&bias[c]);
            float bb1 = __ldg(&bias[c + 1]);
            const float* d = acc[mi][nj];
            float v00 = d[0] + bb0, v01 = d[1] + bb1;
            float v10 = d[2] + bb0, v11 = d[3] + bb1;
            if (RELU) {
                v00 = fmaxf(v00, 0.f); v01 = fmaxf(v01, 0.f);
                v10 = fmaxf(v10, 0.f); v11 = fmaxf(v11, 0.f);
            }
            if (r0 < NN) {
                if (SPLIT) {
                    __nv_bfloat162 H = __floats2bfloat162_rn(v00, v01);
                    __nv_bfloat162 L = __floats2bfloat162_rn(v00 - __bfloat162float(H.x),
                                                             v01 - __bfloat162float(H.y));
                    *(__nv_bfloat162*)(outHh + (size_t)r0 * DD + c) = H;
                    *(__nv_bfloat162*)(outHl + (size_t)r0 * DD + c) = L;
                    *(__half2*)(outH16 + (size_t)r0 * DD + c) = __floats2half2_rn(v00, v01);
                } else {
                    *(float2*)(outF + (size_t)r0 * BN + c) = make_float2(v00, v01);
                }
            }
            if (r0 + 8 < NN) {
                if (SPLIT) {
                    __nv_bfloat162 H = __floats2bfloat162_rn(v10, v11);
                    __nv_bfloat162 L = __floats2bfloat162_rn(v10 - __bfloat162float(H.x),
                                                             v11 - __bfloat162float(H.y));
                    *(__nv_bfloat162*)(outHh + (size_t)(r0 + 8) * DD + c) = H;
                    *(__nv_bfloat162*)(outHl + (size_t)(r0 + 8) * DD + c) = L;
                    *(__half2*)(outH16 + (size_t)(r0 + 8) * DD + c) = __floats2half2_rn(v10, v11);
                } else {
                    *(float2*)(outF + (size_t)(r0 + 8) * BN + c) = make_float2(v10, v11);
                }
            }
        }
    }
}

// ================= launch (single stream, 10 launches, no memsets) ===========
extern "C" void kernel_launch(void* const* d_in, const int* in_sizes, int n_in,
                              void* d_out, int out_size) {
    (void)in_sizes; (void)n_in; (void)out_size;
    const float* x  = (const float*)d_in[0];
    const int*   ei = (const int*)d_in[1];
    const float* ew = (const float*)d_in[2];
    const float* W0 = (const float*)d_in[3];
    const float* b0 = (const float*)d_in[4];
    const float* W1 = (const float*)d_in[5];
    const float* b1 = (const float*)d_in[6];
    const float* W2 = (const float*)d_in[7];
    const float* b2 = (const float*)d_in[8];
    float* out = (float*)d_out;

    void *p_xf16, *p_hf16;
    void *p_xhA, *p_xlA, *p_xhB, *p_xlB;
    void *p_wh0, *p_wl0, *p_wh1, *p_wl1, *p_wh2, *p_wl2;
    cudaGetSymbolAddress(&p_xf16, g_xf16);
    cudaGetSymbolAddress(&p_hf16, g_hf16);
    cudaGetSymbolAddress(&p_xhA, g_xhA);
    cudaGetSymbolAddress(&p_xlA, g_xlA);
    cudaGetSymbolAddress(&p_xhB, g_xhB);
    cudaGetSymbolAddress(&p_xlB, g_xlB);
    cudaGetSymbolAddress(&p_wh0, g_Wh0);
    cudaGetSymbolAddress(&p_wl0, g_Wl0);
    cudaGetSymbolAddress(&p_wh1, g_Wh1);
    cudaGetSymbolAddress(&p_wl1, g_Wl1);
    cudaGetSymbolAddress(&p_wh2, g_Wh2);
    cudaGetSymbolAddress(&p_wl2, g_Wl2);

    const int SMEM128 = 2 * (2 * 128 * 80 + 2 * 128 * 80);   // 81920
    const int SMEM64  = 2 * (2 * 128 * 80 + 2 * 64 * 80);    // 61440
    cudaFuncSetAttribute(tgemm_kernel<128, true, true>,
                         cudaFuncAttributeMaxDynamicSharedMemorySize, SMEM128);
    cudaFuncSetAttribute(tgemm_kernel<64, false, false>,
                         cudaFuncAttributeMaxDynamicSharedMemorySize, SMEM64);

    const int totPrep = NN * DD / 4 + 2 * 128 * KK + 64 * KK;
    const int aggBlocks  = (NN + 7) / 8;
    const int gemmBlocks = (NN + 127) / 128;

    // launch order fixed so ncu (-s 5) samples agg_kernel
    count_kernel<<<(NE / 4 + 255) / 256, 256>>>(ei);                 // 1
    prep_all<<<(totPrep + 255) / 256, 256>>>(x, W0, W1, W2);         // 2
    scan_lb<<<NBLK, 1024>>>();                                       // 3
    fill_kernel<<<(NE / 4 + 255) / 256, 256>>>(ei, ew);              // 4

    // layer 0
    agg_kernel<<<aggBlocks, 256>>>((const __half*)p_xf16);           // 5 <- profiled
    tgemm_kernel<128, true, true><<<gemmBlocks, 256, SMEM128>>>(
        (const __nv_bfloat16*)p_xhA, (const __nv_bfloat16*)p_xlA,
        (const __nv_bfloat16*)p_wh0, (const __nv_bfloat16*)p_wl0,
        b0, nullptr, (__nv_bfloat16*)p_xhB, (__nv_bfloat16*)p_xlB, (__half*)p_hf16);

    // layer 1
    agg_kernel<<<aggBlocks, 256>>>((const __half*)p_hf16);
    tgemm_kernel<128, true, true><<<gemmBlocks, 256, SMEM128>>>(
        (const __nv_bfloat16*)p_xhB, (const __nv_bfloat16*)p_xlB,
        (const __nv_bfloat16*)p_wh1, (const __nv_bfloat16*)p_wl1,
        b1, nullptr, (__nv_bfloat16*)p_xhA, (__nv_bfloat16*)p_xlA, (__half*)p_hf16);

    // layer 2
    agg_kernel<<<aggBlocks, 256>>>((const __half*)p_hf16);
    tgemm_kernel<64, false, false><<<gemmBlocks, 256, SMEM64>>>(
        (const __nv_bfloat16*)p_xhA, (const __nv_bfloat16*)p_xlA,
        (const __nv_bfloat16*)p_wh2, (const __nv_bfloat16*)p_wl2,
        b2, out, nullptr, nullptr, nullptr);
}

// round 13
// speedup vs baseline: 1.2549x; 1.0739x over previous
#include <cuda_runtime.h>
#include <cuda_bf16.h>
#include <cuda_fp16.h>
#include <cstdint>
#include <cstddef>

#define NN   50000
#define NE   800000
#define DD   128
#define KK   256
#define NBLK 49          // ceil(NN/1024)

// ================= low-level helpers =================
__device__ __forceinline__ uint32_t smem_u32(const void* p) {
    uint32_t a;
    asm("{ .reg .u64 t; cvta.to.shared.u64 t, %1; cvt.u32.u64 %0, t; }" : "=r"(a) : "l"(p));
    return a;
}
__device__ __forceinline__ void ldsm4(uint32_t* r, uint32_t addr) {
    asm volatile("ldmatrix.sync.aligned.m8n8.x4.shared.b16 {%0,%1,%2,%3}, [%4];"
                 : "=r"(r[0]), "=r"(r[1]), "=r"(r[2]), "=r"(r[3]) : "r"(addr));
}
__device__ __forceinline__ void mma16816(float* d, const uint32_t* a, uint32_t b0, uint32_t b1) {
    asm volatile(
        "mma.sync.aligned.m16n8k16.row.col.f32.bf16.bf16.f32 "
        "{%0,%1,%2,%3}, {%4,%5,%6,%7}, {%8,%9}, {%0,%1,%2,%3};"
        : "+f"(d[0]), "+f"(d[1]), "+f"(d[2]), "+f"(d[3])
        : "r"(a[0]), "r"(a[1]), "r"(a[2]), "r"(a[3]), "r"(b0), "r"(b1));
}
__device__ __forceinline__ void cpa16(uint32_t dst, const void* src, int sz) {
    asm volatile("cp.async.cg.shared.global [%0], [%1], 16, %2;"
                 :: "r"(dst), "l"(src), "r"(sz));
}
#define CPA_COMMIT() asm volatile("cp.async.commit_group;" ::: "memory")

// ================= device scratch =================
__device__ int   g_cnt[NN];              // zeroed by agg (prev run); static-zero run 1
__device__ int   g_off[NN + 1];
__device__ volatile int g_bsumV[NBLK];
__device__ volatile int g_bflag[NBLK];   // reset by fill (after scan_lb completes)
__device__ int2  g_edge[NE];             // interleaved (col, weight-bits)
__device__ __half g_xf16[NN * DD];
__device__ __half g_hf16[NN * DD];
__device__ __nv_bfloat16 g_xhA[NN * DD], g_xlA[NN * DD];
__device__ __nv_bfloat16 g_xhB[NN * DD], g_xlB[NN * DD];
__device__ __nv_bfloat16 g_ah[NN * DD],  g_al[NN * DD];
__device__ __nv_bfloat16 g_Wh0[128 * KK], g_Wl0[128 * KK];
__device__ __nv_bfloat16 g_Wh1[128 * KK], g_Wl1[128 * KK];
__device__ __nv_bfloat16 g_Wh2[64 * KK],  g_Wl2[64 * KK];

// ========== prep_all: split x (bf16 hi/lo + fp16) AND split weights ==========
__global__ void prep_all(const float* __restrict__ x,
                         const float* __restrict__ W0,
                         const float* __restrict__ W1,
                         const float* __restrict__ W2) {
    const int XQ = NN * DD / 4;
    int i = blockIdx.x * 256 + threadIdx.x;
    if (i < XQ) {
        float4 v = ((const float4*)x)[i];
        __nv_bfloat162 h0 = __floats2bfloat162_rn(v.x, v.y);
        __nv_bfloat162 h1 = __floats2bfloat162_rn(v.z, v.w);
        __nv_bfloat162 l0 = __floats2bfloat162_rn(v.x - __bfloat162float(h0.x),
                                                  v.y - __bfloat162float(h0.y));
        __nv_bfloat162 l1 = __floats2bfloat162_rn(v.z - __bfloat162float(h1.x),
                                                  v.w - __bfloat162float(h1.y));
        ((__nv_bfloat162*)g_xhA)[i * 2]     = h0;
        ((__nv_bfloat162*)g_xhA)[i * 2 + 1] = h1;
        ((__nv_bfloat162*)g_xlA)[i * 2]     = l0;
        ((__nv_bfloat162*)g_xlA)[i * 2 + 1] = l1;
        ((__half2*)g_xf16)[i * 2]     = __floats2half2_rn(v.x, v.y);
        ((__half2*)g_xf16)[i * 2 + 1] = __floats2half2_rn(v.z, v.w);
        return;
    }
    int k = i - XQ;
    const int L = 128 * KK;
    float w; __nv_bfloat16 *dh, *dl; int j;
    if (k < L)                    { j = k;         w = W0[j]; dh = g_Wh0; dl = g_Wl0; }
    else if (k < 2 * L)           { j = k - L;     w = W1[j]; dh = g_Wh1; dl = g_Wl1; }
    else if (k < 2 * L + 64 * KK) { j = k - 2 * L; w = W2[j]; dh = g_Wh2; dl = g_Wl2; }
    else return;
    __nv_bfloat16 hi = __float2bfloat16(w);
    __nv_bfloat16 lo = __float2bfloat16(w - __bfloat162float(hi));
    dh[j] = hi;
    dl[j] = lo;
}

// ================= CSR build =================
__global__ void count_kernel(const int* __restrict__ ei) {
    int e4 = blockIdx.x * blockDim.x + threadIdx.x;
    if (e4 >= NE / 4) return;
    int4 r = ((const int4*)ei)[e4];
    atomicAdd(&g_cnt[r.x], 1);
    atomicAdd(&g_cnt[r.y], 1);
    atomicAdd(&g_cnt[r.z], 1);
    atomicAdd(&g_cnt[r.w], 1);
}

// single-kernel decoupled-lookback exclusive scan (49 blocks, all resident)
__global__ void scan_lb() {
    __shared__ int ws[32];
    __shared__ int s_prefix;
    const int tid = threadIdx.x, lane = tid & 31, wid = tid >> 5;
    const int b = blockIdx.x;
    int i = b * 1024 + tid;
    int v = (i < NN) ? g_cnt[i] : 0;

    int incl = v;
    #pragma unroll
    for (int o = 1; o < 32; o <<= 1) {
        int t = __shfl_up_sync(0xffffffffu, incl, o);
        if (lane >= o) incl += t;
    }
    if (lane == 31) ws[wid] = incl;
    __syncthreads();

    if (wid == 0) {
        int wv = ws[lane];
        int s = wv;
        #pragma unroll
        for (int o = 1; o < 32; o <<= 1) {
            int t = __shfl_up_sync(0xffffffffu, s, o);
            if (lane >= o) s += t;
        }
        if (lane == 31) {
            g_bsumV[b] = s;
            __threadfence();
            g_bflag[b] = 1;
        }
        int excl = s - wv;
        int p = 0;
        for (int q = lane; q < b; q += 32) {
            while (g_bflag[q] == 0) { }
            p += g_bsumV[q];
        }
        #pragma unroll
        for (int o = 16; o > 0; o >>= 1) p += __shfl_xor_sync(0xffffffffu, p, o);
        if (lane == 0) s_prefix = p;
        ws[lane] = excl;
    }
    __syncthreads();

    int o = s_prefix + ws[wid] + incl - v;
    if (i < NN) { g_off[i] = o; g_cnt[i] = o; }
    if (b == 0 && tid == 0) g_off[NN] = NE;
}

__global__ void fill_kernel(const int* __restrict__ ei, const float* __restrict__ ew) {
    int e4 = blockIdx.x * blockDim.x + threadIdx.x;
    if (e4 < NBLK) g_bflag[e4] = 0;            // reset lookback flags for next run
    if (e4 >= NE / 4) return;
    int4   r = ((const int4*)ei)[e4];
    int4   c = ((const int4*)(ei + NE))[e4];
    float4 w = ((const float4*)ew)[e4];
    int p;
    p = atomicAdd(&g_cnt[r.x], 1); g_edge[p] = make_int2(c.x, __float_as_int(w.x));
    p = atomicAdd(&g_cnt[r.y], 1); g_edge[p] = make_int2(c.y, __float_as_int(w.y));
    p = atomicAdd(&g_cnt[r.z], 1); g_edge[p] = make_int2(c.z, __float_as_int(w.z));
    p = atomicAdd(&g_cnt[r.w], 1); g_edge[p] = make_int2(c.w, __float_as_int(w.w));
}

// ======= aggregation: warp per node, fp16 gather, MLP=4; also zeroes g_cnt ====
__global__ void agg_kernel(const __half* __restrict__ xin) {
    int gt = blockIdx.x * blockDim.x + threadIdx.x;
    if (gt < NN) g_cnt[gt] = 0;                // reset histogram for next run
    int gw = gt >> 5;
    if (gw >= NN) return;
    const int lane = threadIdx.x & 31;
    const int s = g_off[gw];
    const int e = g_off[gw + 1];
    float4 acc = make_float4(0.f, 0.f, 0.f, 0.f);
    float wsum = 0.f;
    for (int base = s; base < e; base += 32) {
        int nn = min(32, e - base);
        int c = 0; float w = 0.f;
        if (lane < nn) {
            int2 ed = g_edge[base + lane];
            c = ed.x;
            w = __int_as_float(ed.y);
        }
        wsum += w;
        int j = 0;
        for (; j + 4 <= nn; j += 4) {
            int cj0 = __shfl_sync(0xffffffffu, c, j);
            int cj1 = __shfl_sync(0xffffffffu, c, j + 1);
            int cj2 = __shfl_sync(0xffffffffu, c, j + 2);
            int cj3 = __shfl_sync(0xffffffffu, c, j + 3);
            float wj0 = __shfl_sync(0xffffffffu, w, j);
            float wj1 = __shfl_sync(0xffffffffu, w, j + 1);
            float wj2 = __shfl_sync(0xffffffffu, w, j + 2);
            float wj3 = __shfl_sync(0xffffffffu, w, j + 3);
            uint2 u0 = *(const uint2*)(xin + (size_t)cj0 * DD + lane * 4);
            uint2 u1 = *(const uint2*)(xin + (size_t)cj1 * DD + lane * 4);
            uint2 u2 = *(const uint2*)(xin + (size_t)cj2 * DD + lane * 4);
            uint2 u3 = *(const uint2*)(xin + (size_t)cj3 * DD + lane * 4);
            {
                float2 a = __half22float2(*(const __half2*)&u0.x);
                float2 b = __half22float2(*(const __half2*)&u0.y);
                acc.x = fmaf(a.x, wj0, acc.x); acc.y = fmaf(a.y, wj0, acc.y);
                acc.z = fmaf(b.x, wj0, acc.z); acc.w = fmaf(b.y, wj0, acc.w);
            }
            {
                float2 a = __half22float2(*(const __half2*)&u1.x);
                float2 b = __half22float2(*(const __half2*)&u1.y);
                acc.x = fmaf(a.x, wj1, acc.x); acc.y = fmaf(a.y, wj1, acc.y);
                acc.z = fmaf(b.x, wj1, acc.z); acc.w = fmaf(b.y, wj1, acc.w);
            }
            {
                float2 a = __half22float2(*(const __half2*)&u2.x);
                float2 b = __half22float2(*(const __half2*)&u2.y);
                acc.x = fmaf(a.x, wj2, acc.x); acc.y = fmaf(a.y, wj2, acc.y);
                acc.z = fmaf(b.x, wj2, acc.z); acc.w = fmaf(b.y, wj2, acc.w);
            }
            {
                float2 a = __half22float2(*(const __half2*)&u3.x);
                float2 b = __half22float2(*(const __half2*)&u3.y);
                acc.x = fmaf(a.x, wj3, acc.x); acc.y = fmaf(a.y, wj3, acc.y);
                acc.z = fmaf(b.x, wj3, acc.z); acc.w = fmaf(b.y, wj3, acc.w);
            }
        }
        for (; j < nn; ++j) {
            int cj = __shfl_sync(0xffffffffu, c, j);
            float wj = __shfl_sync(0xffffffffu, w, j);
            uint2 u = *(const uint2*)(xin + (size_t)cj * DD + lane * 4);
            float2 a = __half22float2(*(const __half2*)&u.x);
            float2 b = __half22float2(*(const __half2*)&u.y);
            acc.x = fmaf(a.x, wj, acc.x); acc.y = fmaf(a.y, wj, acc.y);
            acc.z = fmaf(b.x, wj, acc.z); acc.w = fmaf(b.y, wj, acc.w);
        }
    }
    #pragma unroll
    for (int o = 16; o > 0; o >>= 1) wsum += __shfl_xor_sync(0xffffffffu, wsum, o);
    float invd = 1.0f / fmaxf(wsum, 1.0f);
    float v0 = acc.x * invd, v1 = acc.y * invd, v2 = acc.z * invd, v3 = acc.w * invd;
    __nv_bfloat162 h01 = __floats2bfloat162_rn(v0, v1);
    __nv_bfloat162 h23 = __floats2bfloat162_rn(v2, v3);
    __nv_bfloat162 l01 = __floats2bfloat162_rn(v0 - __bfloat162float(h01.x),
                                               v1 - __bfloat162float(h01.y));
    __nv_bfloat162 l23 = __floats2bfloat162_rn(v2 - __bfloat162float(h23.x),
                                               v3 - __bfloat162float(h23.y));
    __nv_bfloat162* oh = (__nv_bfloat162*)g_ah + (size_t)gw * 64 + lane * 2;
    __nv_bfloat162* ol = (__nv_bfloat162*)g_al + (size_t)gw * 64 + lane * 2;
    oh[0] = h01; oh[1] = h23;
    ol[0] = l01; ol[1] = l23;
}

// ================= HMMA GEMM: out = [X|Agg] @ W^T + b =================
// BK=32, 8 K-tiles, double-buffered; stage = 40KB (BN=128) -> 2 CTAs/SM.
template <int BN, bool RELU, bool SPLIT>
__global__ void __launch_bounds__(256, 2) tgemm_kernel(
    const __nv_bfloat16* __restrict__ Xh, const __nv_bfloat16* __restrict__ Xl,
    const __nv_bfloat16* __restrict__ Wh, const __nv_bfloat16* __restrict__ Wl,
    const float* __restrict__ bias,
    float* __restrict__ outF,
    __nv_bfloat16* __restrict__ outHh, __nv_bfloat16* __restrict__ outHl,
    __half* __restrict__ outH16)
{
    extern __shared__ __align__(16) char smem[];
    constexpr int PADB  = 80;
    constexpr int ASZ   = 128 * PADB;
    constexpr int BSZ   = BN * PADB;
    constexpr int STAGE = 2 * ASZ + 2 * BSZ;
    constexpr int WARP_N = BN / 4;
    constexpr int NFRAG  = WARP_N / 8;
    constexpr int NLB    = NFRAG / 2;
    constexpr int BLOADS = (BN * 4) / 256;

    const int tid  = threadIdx.x;
    const int lane = tid & 31;
    const int wid  = tid >> 5;
    const int wm   = wid >> 2;
    const int wn   = wid & 3;
    const int m0   = blockIdx.x * 128;

    const uint32_t sbase = smem_u32(smem);
    const uint32_t offA = (uint32_t)((wm * 64 + (lane & 15)) * PADB + (lane >> 4) * 16);
    const uint32_t offB = (uint32_t)((wn * WARP_N + (lane & 7) + ((lane >> 4) << 3)) * PADB
                                     + (lane & 8) * 2);

    float acc[4][NFRAG][4];
    #pragma unroll
    for (int i = 0; i < 4; ++i)
        #pragma unroll
        for (int j = 0; j < NFRAG; ++j)
            #pragma unroll
            for (int q = 0; q < 4; ++q) acc[i][j][q] = 0.f;

    auto issue = [&](int t, int b) {
        const uint32_t st = sbase + b * STAGE;
        const __nv_bfloat16* axh = (t < 4) ? Xh : g_ah;
        const __nv_bfloat16* axl = (t < 4) ? Xl : g_al;
        const int colb = (t & 3) * 32;
        #pragma unroll
        for (int i = 0; i < 2; ++i) {
            int idx = tid + i * 256;
            int row = idx >> 2, ch = idx & 3;
            int gr = m0 + row;
            int ok = (gr < NN) ? 16 : 0;
            int grc = (gr < NN) ? gr : 0;
            size_t go = (size_t)grc * DD + colb + ch * 8;
            uint32_t sa = (uint32_t)(row * PADB + ch * 16);
            cpa16(st + sa,        axh + go, ok);
            cpa16(st + ASZ + sa,  axl + go, ok);
        }
        #pragma unroll
        for (int i = 0; i < BLOADS; ++i) {
            int idx = tid + i * 256;
            int row = idx >> 2, ch = idx & 3;
            size_t go = (size_t)row * KK + t * 32 + ch * 8;
            uint32_t sa = (uint32_t)(row * PADB + ch * 16);
            cpa16(st + 2 * ASZ + sa,       Wh + go, 16);
            cpa16(st + 2 * ASZ + BSZ + sa, Wl + go, 16);
        }
        CPA_COMMIT();
    };

    auto compute = [&](int b) {
        const uint32_t st  = sbase + b * STAGE;
        const uint32_t pAh = st + offA;
        const uint32_t pAl = st + ASZ + offA;
        const uint32_t pBh = st + 2 * ASZ + offB;
        const uint32_t pBl = st + 2 * ASZ + BSZ + offB;
        #pragma unroll
        for (int kk = 0; kk < 2; ++kk) {
            const int kb = kk * 32;
            uint32_t a[4][4];
            #pragma unroll
            for (int mi = 0; mi < 4; ++mi) ldsm4(a[mi], pAh + mi * (16 * PADB) + kb);
            uint32_t bh[NLB][4];
            #pragma unroll
            for (int p = 0; p < NLB; ++p) ldsm4(bh[p], pBh + p * (16 * PADB) + kb);
            #pragma unroll
            for (int mi = 0; mi < 4; ++mi)
                #pragma unroll
                for (int p = 0; p < NLB; ++p) {
                    mma16816(acc[mi][p * 2],     a[mi], bh[p][0], bh[p][1]);
                    mma16816(acc[mi][p * 2 + 1], a[mi], bh[p][2], bh[p][3]);
                }
            uint32_t bl[NLB][4];
            #pragma unroll
            for (int p = 0; p < NLB; ++p) ldsm4(bl[p], pBl + p * (16 * PADB) + kb);
            #pragma unroll
            for (int mi = 0; mi < 4; ++mi)
                #pragma unroll
                for (int p = 0; p < NLB; ++p) {
                    mma16816(acc[mi][p * 2],     a[mi], bl[p][0], bl[p][1]);
                    mma16816(acc[mi][p * 2 + 1], a[mi], bl[p][2], bl[p][3]);
                }
            #pragma unroll
            for (int mi = 0; mi < 4; ++mi) ldsm4(a[mi], pAl + mi * (16 * PADB) + kb);
            #pragma unroll
            for (int mi = 0; mi < 4; ++mi)
                #pragma unroll
                for (int p = 0; p < NLB; ++p) {
                    mma16816(acc[mi][p * 2],     a[mi], bh[p][0], bh[p][1]);
                    mma16816(acc[mi][p * 2 + 1], a[mi], bh[p][2], bh[p][3]);
                }
        }
    };

    issue(0, 0);
    issue(1, 1);
    #pragma unroll 1
    for (int t = 0; t < 8; ++t) {
        if (t < 7) asm volatile("cp.async.wait_group 1;" ::: "memory");
        else       asm volatile("cp.async.wait_group 0;" ::: "memory");
        __syncthreads();
        compute(t & 1);
        __syncthreads();
        if (t < 6) issue(t + 2, t & 1);
    }

    #pragma unroll
    for (int mi = 0; mi < 4; ++mi) {
        int r0 = m0 + wm * 64 + mi * 16 + (lane >> 2);
        #pragma unroll
        for (int nj = 0; nj < NFRAG; ++nj) {
            int c = wn * WARP_N + nj * 8 + (lane & 3) * 2;
            float bb0 = __ldg(&bias[c]);
            float bb1 = __ldg(&bias[c + 1]);
            const float* d = acc[mi][nj];
            float v00 = d[0] + bb0, v01 = d[1] + bb1;
            float v10 = d[2] + bb0, v11 = d[3] + bb1;
            if (RELU) {
                v00 = fmaxf(v00, 0.f); v01 = fmaxf(v01, 0.f);
                v10 = fmaxf(v10, 0.f); v11 = fmaxf(v11, 0.f);
            }
            if (r0 < NN) {
                if (SPLIT) {
                    __nv_bfloat162 H = __floats2bfloat162_rn(v00, v01);
                    __nv_bfloat162 L = __floats2bfloat162_rn(v00 - __bfloat162float(H.x),
                                                             v01 - __bfloat162float(H.y));
                    *(__nv_bfloat162*)(outHh + (size_t)r0 * DD + c) = H;
                    *(__nv_bfloat162*)(outHl + (size_t)r0 * DD + c) = L;
                    *(__half2*)(outH16 + (size_t)r0 * DD + c) = __floats2half2_rn(v00, v01);
                } else {
                    *(float2*)(outF + (size_t)r0 * BN + c) = make_float2(v00, v01);
                }
            }
            if (r0 + 8 < NN) {
                if (SPLIT) {
                    __nv_bfloat162 H = __floats2bfloat162_rn(v10, v11);
                    __nv_bfloat162 L = __floats2bfloat162_rn(v10 - __bfloat162float(H.x),
                                                             v11 - __bfloat162float(H.y));
                    *(__nv_bfloat162*)(outHh + (size_t)(r0 + 8) * DD + c) = H;
                    *(__nv_bfloat162*)(outHl + (size_t)(r0 + 8) * DD + c) = L;
                    *(__half2*)(outH16 + (size_t)(r0 + 8) * DD + c) = __floats2half2_rn(v10, v11);
                } else {
                    *(float2*)(outF + (size_t)(r0 + 8) * BN + c) = make_float2(v10, v11);
                }
            }
        }
    }
}

// ================= launch =================
extern "C" void kernel_launch(void* const* d_in, const int* in_sizes, int n_in,
                              void* d_out, int out_size) {
    (void)in_sizes; (void)n_in; (void)out_size;
    const float* x  = (const float*)d_in[0];
    const int*   ei = (const int*)d_in[1];
    const float* ew = (const float*)d_in[2];
    const float* W0 = (const float*)d_in[3];
    const float* b0 = (const float*)d_in[4];
    const float* W1 = (const float*)d_in[5];
    const float* b1 = (const float*)d_in[6];
    const float* W2 = (const float*)d_in[7];
    const float* b2 = (const float*)d_in[8];
    float* out = (float*)d_out;

    void *p_xf16, *p_hf16;
    void *p_xhA, *p_xlA, *p_xhB, *p_xlB;
    void *p_wh0, *p_wl0, *p_wh1, *p_wl1, *p_wh2, *p_wl2;
    cudaGetSymbolAddress(&p_xf16, g_xf16);
    cudaGetSymbolAddress(&p_hf16, g_hf16);
    cudaGetSymbolAddress(&p_xhA, g_xhA);
    cudaGetSymbolAddress(&p_xlA, g_xlA);
    cudaGetSymbolAddress(&p_xhB, g_xhB);
    cudaGetSymbolAddress(&p_xlB, g_xlB);
    cudaGetSymbolAddress(&p_wh0, g_Wh0);
    cudaGetSymbolAddress(&p_wl0, g_Wl0);
    cudaGetSymbolAddress(&p_wh1, g_Wh1);
    cudaGetSymbolAddress(&p_wl1, g_Wl1);
    cudaGetSymbolAddress(&p_wh2, g_Wh2);
    cudaGetSymbolAddress(&p_wl2, g_Wl2);

    const int SMEM128 = 2 * (2 * 128 * 80 + 2 * 128 * 80);   // 81920
    const int SMEM64  = 2 * (2 * 128 * 80 + 2 * 64 * 80);    // 61440
    cudaFuncSetAttribute(tgemm_kernel<128, true, true>,
                         cudaFuncAttributeMaxDynamicSharedMemorySize, SMEM128);
    cudaFuncSetAttribute(tgemm_kernel<64, false, false>,
                         cudaFuncAttributeMaxDynamicSharedMemorySize, SMEM64);

    // side stream + events (created once, outside capture; reused inside capture)
    static cudaStream_t s1 = nullptr;
    static cudaEvent_t ev_fork = nullptr, ev_join = nullptr;
    if (s1 == nullptr) {
        cudaStreamCreateWithFlags(&s1, cudaStreamNonBlocking);
        cudaEventCreateWithFlags(&ev_fork, cudaEventDisableTiming);
        cudaEventCreateWithFlags(&ev_join, cudaEventDisableTiming);
    }

    const int totPrep = NN * DD / 4 + 2 * 128 * KK + 64 * KK;
    const int aggBlocks  = (NN + 7) / 8;
    const int gemmBlocks = (NN + 127) / 128;

    // fork: CSR build on s1, feature/weight prep on main
    cudaEventRecord(ev_fork, 0);
    cudaStreamWaitEvent(s1, ev_fork, 0);
    count_kernel<<<(NE / 4 + 255) / 256, 256, 0, s1>>>(ei);
    scan_lb<<<NBLK, 1024, 0, s1>>>();
    fill_kernel<<<(NE / 4 + 255) / 256, 256, 0, s1>>>(ei, ew);
    cudaEventRecord(ev_join, s1);

    prep_all<<<(totPrep + 255) / 256, 256>>>(x, W0, W1, W2);

    cudaStreamWaitEvent(0, ev_join, 0);   // join before aggregation

    // layer 0
    agg_kernel<<<aggBlocks, 256>>>((const __half*)p_xf16);
    tgemm_kernel<128, true, true><<<gemmBlocks, 256, SMEM128>>>(
        (const __nv_bfloat16*)p_xhA, (const __nv_bfloat16*)p_xlA,
        (const __nv_bfloat16*)p_wh0, (const __nv_bfloat16*)p_wl0,
        b0, nullptr, (__nv_bfloat16*)p_xhB, (__nv_bfloat16*)p_xlB, (__half*)p_hf16);

    // layer 1
    agg_kernel<<<aggBlocks, 256>>>((const __half*)p_hf16);
    tgemm_kernel<128, true, true><<<gemmBlocks, 256, SMEM128>>>(
        (const __nv_bfloat16*)p_xhB, (const __nv_bfloat16*)p_xlB,
        (const __nv_bfloat16*)p_wh1, (const __nv_bfloat16*)p_wl1,
        b1, nullptr, (__nv_bfloat16*)p_xhA, (__nv_bfloat16*)p_xlA, (__half*)p_hf16);

    // layer 2
    agg_kernel<<<aggBlocks, 256>>>((const __half*)p_hf16);
    tgemm_kernel<64, false, false><<<gemmBlocks, 256, SMEM64>>>(
        (const __nv_bfloat16*)p_xhA, (const __nv_bfloat16*)p_xlA,
        (const __nv_bfloat16*)p_wh2, (const __nv_bfloat16*)p_wl2,
        b2, out, nullptr, nullptr, nullptr);
}